// round 16
// baseline (speedup 1.0000x reference)
#include <cuda_runtime.h>
#include <cuda_bf16.h>
#include <math.h>
#include <cstdint>

#define B_   16
#define N_   2048
#define DIN  2
#define U_   64
#define F_   66        // concat feature dim
#define FP   68        // padded feature stride
#define E_   32768
#define NTOT (B_*N_)
#define NB   80        // padded N for adp tensor GEMM

__device__ __forceinline__ uint32_t smem_to_u32(const void* p) {
    uint32_t a;
    asm("{ .reg .u64 t; cvta.to.shared.u64 t, %1; cvt.u32.u64 %0, t; }" : "=r"(a) : "l"(p));
    return a;
}
__device__ __forceinline__ uint32_t pack_bf16x2(float lo, float hi) {
    uint32_t r;
    asm("cvt.rn.bf16x2.f32 %0, %1, %2;" : "=r"(r) : "f"(hi), "f"(lo));
    return r;
}
__device__ __forceinline__ uint32_t f2tf32(float v) {
    uint32_t r;
    asm("cvt.rna.tf32.f32 %0, %1;" : "=r"(r) : "f"(v));
    return r;
}
__device__ __forceinline__ void ldmatrix_x4(uint32_t* r, uint32_t addr) {
    asm volatile("ldmatrix.sync.aligned.m8n8.x4.shared.b16 {%0,%1,%2,%3}, [%4];"
        : "=r"(r[0]), "=r"(r[1]), "=r"(r[2]), "=r"(r[3]) : "r"(addr));
}
__device__ __forceinline__ void ldmatrix_x2(uint32_t* r, uint32_t addr) {
    asm volatile("ldmatrix.sync.aligned.m8n8.x2.shared.b16 {%0,%1}, [%2];"
        : "=r"(r[0]), "=r"(r[1]) : "r"(addr));
}
__device__ __forceinline__ void mma_bf16(float* c, const uint32_t* a, const uint32_t* b) {
    asm volatile("mma.sync.aligned.m16n8k16.row.col.f32.bf16.bf16.f32 "
        "{%0,%1,%2,%3}, {%4,%5,%6,%7}, {%8,%9}, {%0,%1,%2,%3};"
        : "+f"(c[0]), "+f"(c[1]), "+f"(c[2]), "+f"(c[3])
        : "r"(a[0]), "r"(a[1]), "r"(a[2]), "r"(a[3]), "r"(b[0]), "r"(b[1]));
}
__device__ __forceinline__ void mma_tf32(float* c, const uint32_t* a, const uint32_t* b) {
    asm volatile("mma.sync.aligned.m16n8k8.row.col.f32.tf32.tf32.f32 "
        "{%0,%1,%2,%3}, {%4,%5,%6,%7}, {%8,%9}, {%0,%1,%2,%3};"
        : "+f"(c[0]), "+f"(c[1]), "+f"(c[2]), "+f"(c[3])
        : "r"(a[0]), "r"(a[1]), "r"(a[2]), "r"(a[3]), "r"(b[0]), "r"(b[1]));
}
#define CP_ASYNC16(smem, gptr) \
    asm volatile("cp.async.cg.shared.global [%0], [%1], 16;" :: "r"(smem), "l"(gptr) : "memory")
#define CP_COMMIT() asm volatile("cp.async.commit_group;" ::: "memory")
#define CP_WAIT(n)  asm volatile("cp.async.wait_group %0;" :: "n"(n) : "memory")

// ================= scratch =================
static __device__ float g_x [B_*N_*FP];
static __device__ float g_x1[B_*N_*FP];
static __device__ float g_x2[B_*N_*FP];
static __device__ float g_x2b[B_*N_*FP];                  // K-split partial (pass 2)
static __device__ float g_s2[NTOT*U_];
static __device__ float g_u [NTOT*U_];
static __device__ __nv_bfloat16 g_adp[(size_t)B_*N_*N_];  // bf16 adp written by pass 1
static __device__ __nv_bfloat16 g_xt[B_*NB*N_];           // transposed bf16 features
static __device__ uint32_t g_wp_ru[216*128];
static __device__ uint32_t g_wp_c [216*64];
static __device__ int   g_cnt[N_];
static __device__ int   g_off[N_ + 1];
static __device__ int   g_ccol[E_];
static __device__ float g_cval[E_];

// ================= prep: zero g_cnt + W permute/tf32 =================
__global__ void k_prep(const float* __restrict__ W_ru, const float* __restrict__ W_c) {
    int idx = blockIdx.x * blockDim.x + threadIdx.x;
    if (idx < N_) g_cnt[idx] = 0;
    if (idx < 216 * 128) {
        int kk = idx >> 7, o = idx & 127;
        int m = kk / 72, f = kk - m * 72;
        float v = (f < F_) ? W_ru[(f * 3 + m) * 128 + o] : 0.f;
        g_wp_ru[idx] = f2tf32(v);
    } else {
        int j = idx - 216 * 128;
        if (j < 216 * 64) {
            int kk = j >> 6, o = j & 63;
            int m = kk / 72, f = kk - m * 72;
            float v = (f < F_) ? W_c[(f * 3 + m) * 64 + o] : 0.f;
            g_wp_c[j] = f2tf32(v);
        }
    }
}

// ================= CSR scan =================
__global__ __launch_bounds__(1024) void k_scan() {
    __shared__ int sa[N_], sb[N_];
    int t = threadIdx.x;
    sa[t] = g_cnt[t];
    sa[t + 1024] = g_cnt[t + 1024];
    __syncthreads();
    int* src = sa; int* dst = sb;
    for (int d = 1; d < N_; d <<= 1) {
        for (int k = t; k < N_; k += 1024) {
            int v = src[k];
            if (k >= d) v += src[k - d];
            dst[k] = v;
        }
        __syncthreads();
        int* tmp = src; src = dst; dst = tmp;
    }
    int e0 = (t == 0) ? 0 : src[t - 1];
    int e1 = src[t + 1023];
    g_off[t] = e0;        g_off[t + 1024] = e1;
    g_cnt[t] = e0;        g_cnt[t + 1024] = e1;
    if (t == 0) g_off[N_] = src[N_ - 1];
}

// ================= fused build: g_x + g_xt [+ hist in pass 1] =================
template <bool USE_S2>
__global__ __launch_bounds__(256) void k_build_xt(const float* __restrict__ in,
                                                  const float* __restrict__ st,
                                                  const int* __restrict__ rows) {
    __shared__ float sx[64][69];
    int tid = threadIdx.x;
    int b   = blockIdx.x >> 5;
    int m0  = (blockIdx.x & 31) << 6;
    int bn0 = (b << 11) + m0;

    if (!USE_S2) {
        if (blockIdx.x < E_ / 256) {
            int e = blockIdx.x * 256 + tid;
            atomicAdd(&g_cnt[rows[e]], 1);
        }
    }

    const float* S = USE_S2 ? g_s2 : st;
    for (int q = tid; q < 64 * U_; q += 256) {
        int r = q >> 6, c = q & 63;
        sx[r][2 + c] = S[(bn0 + r) * U_ + c];
    }
    for (int q = tid; q < 64 * DIN; q += 256) {
        int r = q >> 1, j = q & 1;
        sx[r][j] = in[(b << 12) + (m0 + r) * DIN + j];
    }
    __syncthreads();
    for (int q = tid; q < 64 * FP; q += 256) {
        int r = q / FP, f = q - r * FP;
        g_x[(size_t)(bn0 + r) * FP + f] = (f < F_) ? sx[r][f] : 0.f;
    }
    for (int q = tid; q < NB * 64; q += 256) {
        int f = q >> 6, ml = q & 63;
        float v = (f < F_) ? sx[ml][f] : 0.f;
        g_xt[((size_t)(b * NB + f) << 11) + m0 + ml] = __float2bfloat16(v);
    }
}

// ================= spmm =================
__global__ __launch_bounds__(128) void k_spmm() {
    int n = blockIdx.x;
    int s = g_off[n], e = g_off[n + 1];
    int tid = threadIdx.x;
    float acc[9];
#pragma unroll
    for (int j = 0; j < 9; j++) acc[j] = 0.f;

    __shared__ int   scol[128];
    __shared__ float sval[128];

    for (int base = s; base < e; base += 128) {
        int cnt = min(128, e - base);
        if (tid < cnt) { scol[tid] = g_ccol[base + tid]; sval[tid] = g_cval[base + tid]; }
        __syncthreads();
        for (int t = 0; t < cnt; t++) {
            int   c = scol[t];
            float v = sval[t];
#pragma unroll
            for (int j = 0; j < 9; j++) {
                int i = tid + j * 128;
                if (i < B_ * F_) {
                    int bb = i / F_, f = i - bb * F_;
                    acc[j] += v * g_x[(bb * N_ + c) * FP + f];
                }
            }
        }
        __syncthreads();
    }
#pragma unroll
    for (int j = 0; j < 9; j++) {
        int i = tid + j * 128;
        if (i < B_ * F_) {
            int bb = i / F_, f = i - bb * F_;
            g_x1[(bb * N_ + n) * FP + f] = acc[j];
        }
    }
}

// ================= gemm pass 1: 512-thread CTAs, cp.async + cvt + MMA [+ scatter] ===
// 16 warps 8(M) x 2(N); warp tile 16 x 40; grid 256; forced 2 CTAs/SM (32 warps).
#define KT       32
#define TILES    (N_ / KT)
#define ASTRIDE  40
#define BSTRIDE  40
#define CSTG     3
#define SF_STG   (128 * KT * 4)
#define SB1_STG  (NB * BSTRIDE * 2)
#define SABF_B   (128 * ASTRIDE * 2)
#define GEMM1_SMEM (CSTG * (SF_STG + SB1_STG) + SABF_B)   // 78592 B

__global__ __launch_bounds__(512, 2) void k_gemm_cvt(const float* __restrict__ adp,
                                                     const int* __restrict__ rows,
                                                     const int* __restrict__ cols,
                                                     const float* __restrict__ vals) {
    extern __shared__ char smem1[];
    uint32_t sFaddr  = smem_to_u32(smem1);
    uint32_t sBaddr  = sFaddr + CSTG * SF_STG;
    uint32_t sAbf    = sBaddr + CSTG * SB1_STG;

    int tid  = threadIdx.x;
    int lane = tid & 31;
    int wid  = tid >> 5;
    int wm   = wid >> 1, wn = wid & 1;
    int m0w  = wm * 16, n0w = wn * 40;

    // fused CSR scatter: blocks 0..63 place 512 edges each
    if (blockIdx.x < E_ / 512) {
        int e = blockIdx.x * 512 + tid;
        int r = rows[e];
        int p = atomicAdd(&g_cnt[r], 1);
        g_ccol[p] = cols[e];
        g_cval[p] = vals[e];
    }

    int b  = blockIdx.x >> 4;
    int m0 = (blockIdx.x & 15) << 7;
    const float* A = adp + (size_t)b * N_ * N_;
    __nv_bfloat16* Aout = g_adp + (size_t)b * N_ * N_;
    const __nv_bfloat16* XT = g_xt + ((size_t)b * NB << 11);

    float acc[5][4];
#pragma unroll
    for (int ni = 0; ni < 5; ni++)
#pragma unroll
        for (int c = 0; c < 4; c++) acc[ni][c] = 0.f;

    int br0 = tid >> 2, bc0 = tid & 3;   // valid for tid < 320

    auto issue_stage = [&](int slot, int tile) {
        uint32_t fS = sFaddr + slot * SF_STG;
        uint32_t bS = sBaddr + slot * SB1_STG;
        int kt = tile * KT;
#pragma unroll
        for (int i = 0; i < 2; i++) {
            int q = tid + i * 512;
            int row = q >> 3, c4 = q & 7;
            CP_ASYNC16(fS + (uint32_t)(row * KT + c4 * 4) * 4,
                       A + (((size_t)(m0 + row)) << 11) + kt + c4 * 4);
        }
        if (tid < 320)
            CP_ASYNC16(bS + (uint32_t)(br0 * BSTRIDE + bc0 * 8) * 2,
                       XT + (((size_t)br0) << 11) + kt + bc0 * 8);
    };

#pragma unroll
    for (int s = 0; s < CSTG; s++) {
        issue_stage(s, s);
        CP_COMMIT();
    }

    int slot = 0;
    for (int t = 0; t < TILES; t++) {
        CP_WAIT(CSTG - 1);
        __syncthreads();

        uint32_t fS = sFaddr + slot * SF_STG;
        int kt = t * KT;
#pragma unroll
        for (int i = 0; i < 2; i++) {
            int q = tid + i * 512;
            int row = q >> 3, c4 = q & 7;
            float vx, vy, vz, vw;
            asm volatile("ld.shared.v4.f32 {%0,%1,%2,%3}, [%4];"
                : "=f"(vx), "=f"(vy), "=f"(vz), "=f"(vw)
                : "r"(fS + (uint32_t)(row * KT + c4 * 4) * 4));
            uint32_t p0 = pack_bf16x2(vx, vy);
            uint32_t p1 = pack_bf16x2(vz, vw);
            asm volatile("st.shared.v2.b32 [%0], {%1, %2};"
                :: "r"(sAbf + (uint32_t)(row * ASTRIDE + c4 * 4) * 2), "r"(p0), "r"(p1) : "memory");
            *(uint2*)&Aout[(((size_t)(m0 + row)) << 11) + kt + c4 * 4] = make_uint2(p0, p1);
        }
        __syncthreads();

        uint32_t bS = sBaddr + slot * SB1_STG;
#pragma unroll
        for (int ks = 0; ks < 2; ks++) {
            uint32_t afr[4];
            {
                uint32_t ad = sAbf + (uint32_t)((m0w + (lane & 15)) * ASTRIDE
                              + ks * 16 + (lane >> 4) * 8) * 2;
                ldmatrix_x4(afr, ad);
            }
            uint32_t bfr[5][2];
#pragma unroll
            for (int ni = 0; ni < 5; ni++) {
                uint32_t bd = bS + (uint32_t)((n0w + ni * 8 + (lane & 7)) * BSTRIDE
                              + ks * 16 + ((lane >> 3) & 1) * 8) * 2;
                ldmatrix_x2(bfr[ni], bd);
            }
#pragma unroll
            for (int ni = 0; ni < 5; ni++)
                mma_bf16(acc[ni], afr, bfr[ni]);
        }
        __syncthreads();

        if (t + CSTG < TILES) issue_stage(slot, t + CSTG);
        CP_COMMIT();
        if (++slot == CSTG) slot = 0;
    }

#pragma unroll
    for (int ni = 0; ni < 5; ni++) {
        int col = n0w + ni * 8 + (lane & 3) * 2;
        if (col < F_) {
            int r0 = m0 + m0w + (lane >> 2);
            size_t base0 = ((size_t)(b << 11) + r0) * FP + col;
            *(float2*)&g_x2[base0]          = make_float2(acc[ni][0], acc[ni][1]);
            *(float2*)&g_x2[base0 + 8 * FP] = make_float2(acc[ni][2], acc[ni][3]);
        }
    }
}

// ================= gemm pass 2: 512-thread CTAs, cp.async 3-stage, K-split x2 =======
#define STG2     3
#define TILES2   (N_ / KT / 2)
#define A2_STG   (128 * ASTRIDE * 2)
#define B2_STG   (NB  * BSTRIDE * 2)
#define GEMM2_SMEM (STG2 * (A2_STG + B2_STG))   // 49920 B

__global__ __launch_bounds__(512, 2) void k_gemm_bf() {
    extern __shared__ char smem[];
    uint32_t sAaddr = smem_to_u32(smem);
    uint32_t sBaddr = sAaddr + STG2 * A2_STG;

    int tid  = threadIdx.x;
    int lane = tid & 31;
    int wid  = tid >> 5;
    int wm   = wid >> 1, wn = wid & 1;
    int m0w  = wm * 16, n0w = wn * 40;

    int b  = blockIdx.x >> 5;
    int m0 = ((blockIdx.x >> 1) & 15) << 7;
    int kh = blockIdx.x & 1;
    int kbase = kh << 10;
    const __nv_bfloat16* Ab = g_adp + (size_t)b * N_ * N_;
    const __nv_bfloat16* XT = g_xt + ((size_t)b * NB << 11);
    float* X2out = kh ? g_x2b : g_x2;

    float acc[5][4];
#pragma unroll
    for (int ni = 0; ni < 5; ni++)
#pragma unroll
        for (int c = 0; c < 4; c++) acc[ni][c] = 0.f;

    int ar0 = tid >> 2, ac0 = tid & 3;   // 512 A tasks, 1 per thread
    int br0 = tid >> 2, bc0 = tid & 3;   // 320 B tasks, tid < 320

    auto issue_stage = [&](int slot, int tile) {
        uint32_t aS = sAaddr + slot * A2_STG;
        uint32_t bS = sBaddr + slot * B2_STG;
        int kt = kbase + tile * KT;
        CP_ASYNC16(aS + (uint32_t)(ar0 * ASTRIDE + ac0 * 8) * 2,
                   Ab + (((size_t)(m0 + ar0)) << 11) + kt + ac0 * 8);
        if (tid < 320)
            CP_ASYNC16(bS + (uint32_t)(br0 * BSTRIDE + bc0 * 8) * 2,
                       XT + (((size_t)br0) << 11) + kt + bc0 * 8);
    };

#pragma unroll
    for (int s = 0; s < STG2; s++) {
        issue_stage(s, s);
        CP_COMMIT();
    }

    int slot = 0;
    for (int t = 0; t < TILES2; t++) {
        CP_WAIT(STG2 - 1);
        __syncthreads();

        uint32_t aS = sAaddr + slot * A2_STG;
        uint32_t bS = sBaddr + slot * B2_STG;
#pragma unroll
        for (int ks = 0; ks < 2; ks++) {
            uint32_t afr[4];
            {
                uint32_t ad = aS + (uint32_t)((m0w + (lane & 15)) * ASTRIDE
                              + ks * 16 + (lane >> 4) * 8) * 2;
                ldmatrix_x4(afr, ad);
            }
            uint32_t bfr[5][2];
#pragma unroll
            for (int ni = 0; ni < 5; ni++) {
                uint32_t bd = bS + (uint32_t)((n0w + ni * 8 + (lane & 7)) * BSTRIDE
                              + ks * 16 + ((lane >> 3) & 1) * 8) * 2;
                ldmatrix_x2(bfr[ni], bd);
            }
#pragma unroll
            for (int ni = 0; ni < 5; ni++)
                mma_bf16(acc[ni], afr, bfr[ni]);
        }
        __syncthreads();

        if (t + STG2 < TILES2) issue_stage(slot, t + STG2);
        CP_COMMIT();
        if (++slot == STG2) slot = 0;
    }

#pragma unroll
    for (int ni = 0; ni < 5; ni++) {
        int col = n0w + ni * 8 + (lane & 3) * 2;
        if (col < F_) {
            int r0 = m0 + m0w + (lane >> 2);
            size_t base0 = ((size_t)(b << 11) + r0) * FP + col;
            *(float2*)&X2out[base0]          = make_float2(acc[ni][0], acc[ni][1]);
            *(float2*)&X2out[base0 + 8 * FP] = make_float2(acc[ni][2], acc[ni][3]);
        }
    }
}

// ================= output GEMM (tf32 tensor cores) =================
template <int ON, bool IS_RU>
__global__ __launch_bounds__(256) void k_out_tc(const uint32_t* __restrict__ Wp,
                                                const float* __restrict__ hx,
                                                float* __restrict__ dout) {
    extern __shared__ uint32_t sm[];
    const int ASTR = 76;
    const int BSTR = ON + 4;
    uint32_t* sA = sm;
    uint32_t* sB = sm + 64 * ASTR;

    const int WNW   = ON / 32;
    const int MFRAG = (ON == 128) ? 2 : 1;
    const int WTM   = MFRAG * 16;

    int tid = threadIdx.x, lane = tid & 31, wid = tid >> 5;
    int wn = wid % WNW, wm = wid / WNW;
    int row0 = blockIdx.x * 64;
    int g = lane >> 2, tt = lane & 3;

    for (int q = tid; q < 64 * 6; q += 256) {
        int r = q / 6, c = 66 + (q - r * 6);
        sA[r * ASTR + c] = 0;
    }

    float acc[MFRAG][4][4];
#pragma unroll
    for (int mi = 0; mi < MFRAG; mi++)
#pragma unroll
        for (int ni = 0; ni < 4; ni++)
#pragma unroll
            for (int c = 0; c < 4; c++) acc[mi][ni][c] = 0.f;

    for (int m = 0; m < 3; m++) {
        const float* Xb = (m == 0) ? g_x : (m == 1) ? g_x1 : g_x2;
        bool sum2 = (!IS_RU) && (m == 2);
        __syncthreads();
        for (int q = tid; q < 64 * 17; q += 256) {
            int r = q / 17, p = q - r * 17;
            size_t src = (size_t)(row0 + r) * FP;
            uint32_t dst = r * ASTR;
            if (p < 16) {
                float4 v = *(const float4*)&Xb[src + p * 4];
                if (sum2) {
                    float4 w = *(const float4*)&g_x2b[src + p * 4];
                    v.x += w.x; v.y += w.y; v.z += w.z; v.w += w.w;
                }
                uint32_t t0 = f2tf32(v.x), t1 = f2tf32(v.y), t2 = f2tf32(v.z), t3 = f2tf32(v.w);
                *(uint4*)&sA[dst + p * 4] = make_uint4(t0, t1, t2, t3);
            } else {
                float2 v = *(const float2*)&Xb[src + 64];
                if (sum2) {
                    float2 w = *(const float2*)&g_x2b[src + 64];
                    v.x += w.x; v.y += w.y;
                }
                sA[dst + 64] = f2tf32(v.x);
                sA[dst + 65] = f2tf32(v.y);
            }
        }
        for (int q = tid; q < 72 * (ON / 4); q += 256) {
            int r = q / (ON / 4), c4 = q - r * (ON / 4);
            uint4 v = *(const uint4*)&Wp[(m * 72 + r) * ON + c4 * 4];
            *(uint4*)&sB[r * BSTR + c4 * 4] = v;
        }
        __syncthreads();
#pragma unroll
        for (int kt = 0; kt < 9; kt++) {
            int k0 = kt * 8;
            uint32_t af[MFRAG][4];
#pragma unroll
            for (int mi = 0; mi < MFRAG; mi++) {
                int r0 = wm * WTM + mi * 16 + g;
                int kc = k0 + tt;
                af[mi][0] = sA[r0 * ASTR + kc];
                af[mi][1] = sA[(r0 + 8) * ASTR + kc];
                af[mi][2] = sA[r0 * ASTR + kc + 4];
                af[mi][3] = sA[(r0 + 8) * ASTR + kc + 4];
            }
            uint32_t bf[4][2];
#pragma unroll
            for (int ni = 0; ni < 4; ni++) {
                int col = wn * 32 + ni * 8 + g;
                int kr = k0 + tt;
                bf[ni][0] = sB[kr * BSTR + col];
                bf[ni][1] = sB[(kr + 4) * BSTR + col];
            }
#pragma unroll
            for (int mi = 0; mi < MFRAG; mi++)
#pragma unroll
                for (int ni = 0; ni < 4; ni++)
                    mma_tf32(acc[mi][ni], af[mi], bf[ni]);
        }
    }

#pragma unroll
    for (int mi = 0; mi < MFRAG; mi++) {
#pragma unroll
        for (int ni = 0; ni < 4; ni++) {
            int r0  = row0 + wm * WTM + mi * 16 + g;
            int col = wn * 32 + ni * 8 + tt * 2;
#pragma unroll
            for (int h = 0; h < 2; h++) {
                int bn = r0 + h * 8;
#pragma unroll
                for (int cc = 0; cc < 2; cc++) {
                    float v = acc[mi][ni][h * 2 + cc];
                    int o = col + cc;
                    if (IS_RU) {
                        float s = 1.f / (1.f + expf(-v));
                        if (o < U_) g_s2[bn * U_ + o] = s * hx[bn * U_ + o];
                        else        g_u [bn * U_ + (o - U_)] = s;
                    } else {
                        float cv = tanhf(v);
                        int idx = bn * U_ + o;
                        float u = g_u[idx], hh = hx[idx];
                        dout[idx] = u * hh + (1.f - u) * cv;
                    }
                }
            }
        }
    }
}

// ================= launch =================
extern "C" void kernel_launch(void* const* d_in, const int* in_sizes, int n_in,
                              void* d_out, int out_size) {
    const float* inputs = (const float*)d_in[0];
    const float* hx     = (const float*)d_in[1];
    const float* adp    = (const float*)d_in[2];
    const int*   rows   = (const int*)d_in[3];
    const int*   cols   = (const int*)d_in[4];
    const float* vals   = (const float*)d_in[5];
    const float* W_ru   = (const float*)d_in[6];
    const float* W_c    = (const float*)d_in[7];
    float* out = (float*)d_out;
    (void)in_sizes; (void)n_in; (void)out_size;

    const int SMEM_RU = (64 * 76 + 72 * 132) * 4;
    const int SMEM_C  = (64 * 76 + 72 * 68) * 4;
    cudaFuncSetAttribute(k_gemm_cvt, cudaFuncAttributeMaxDynamicSharedMemorySize, GEMM1_SMEM);
    cudaFuncSetAttribute(k_gemm_bf, cudaFuncAttributeMaxDynamicSharedMemorySize, GEMM2_SMEM);
    cudaFuncSetAttribute(k_out_tc<128, true>, cudaFuncAttributeMaxDynamicSharedMemorySize, SMEM_RU);
    cudaFuncSetAttribute(k_out_tc<64, false>, cudaFuncAttributeMaxDynamicSharedMemorySize, SMEM_C);

    uint32_t* wp_ru; cudaGetSymbolAddress((void**)&wp_ru, g_wp_ru);
    uint32_t* wp_c;  cudaGetSymbolAddress((void**)&wp_c,  g_wp_c);

    // ordered so pass-1 gemm is the 4th launch (ncu profiling slot)
    k_prep    <<<162, 256>>>(W_ru, W_c);                   // zero g_cnt + wperm
    k_build_xt<false><<<512, 256>>>(inputs, hx, rows);     // build#1 + hist
    k_scan    <<<1, 1024>>>();
    k_gemm_cvt<<<256, 512, GEMM1_SMEM>>>(adp, rows, cols, vals);  // profiled (+scatter)
    k_spmm    <<<N_, 128>>>();
    k_out_tc<128, true><<<NTOT / 64, 256, SMEM_RU>>>(wp_ru, hx, out);

    // ---- gconv #2 : candidate c ----
    k_build_xt<true><<<512, 256>>>(inputs, hx, rows);
    k_gemm_bf <<<512, 512, GEMM2_SMEM>>>();
    k_spmm    <<<N_, 128>>>();
    k_out_tc<64, false><<<NTOT / 64, 256, SMEM_C>>>(wp_c, hx, out);
}

// round 17
// speedup vs baseline: 1.0893x; 1.0893x over previous
#include <cuda_runtime.h>
#include <cuda_bf16.h>
#include <math.h>
#include <cstdint>

#define B_   16
#define N_   2048
#define DIN  2
#define U_   64
#define F_   66        // concat feature dim
#define FP   68        // padded feature stride
#define E_   32768
#define NTOT (B_*N_)
#define NB   80        // padded N for adp tensor GEMM

__device__ __forceinline__ uint32_t smem_to_u32(const void* p) {
    uint32_t a;
    asm("{ .reg .u64 t; cvta.to.shared.u64 t, %1; cvt.u32.u64 %0, t; }" : "=r"(a) : "l"(p));
    return a;
}
__device__ __forceinline__ uint32_t pack_bf16x2(float lo, float hi) {
    uint32_t r;
    asm("cvt.rn.bf16x2.f32 %0, %1, %2;" : "=r"(r) : "f"(hi), "f"(lo));
    return r;
}
__device__ __forceinline__ uint32_t f2tf32(float v) {
    uint32_t r;
    asm("cvt.rna.tf32.f32 %0, %1;" : "=r"(r) : "f"(v));
    return r;
}
__device__ __forceinline__ void ldmatrix_x4(uint32_t* r, uint32_t addr) {
    asm volatile("ldmatrix.sync.aligned.m8n8.x4.shared.b16 {%0,%1,%2,%3}, [%4];"
        : "=r"(r[0]), "=r"(r[1]), "=r"(r[2]), "=r"(r[3]) : "r"(addr));
}
__device__ __forceinline__ void ldmatrix_x2(uint32_t* r, uint32_t addr) {
    asm volatile("ldmatrix.sync.aligned.m8n8.x2.shared.b16 {%0,%1}, [%2];"
        : "=r"(r[0]), "=r"(r[1]) : "r"(addr));
}
__device__ __forceinline__ void mma_bf16(float* c, const uint32_t* a, const uint32_t* b) {
    asm volatile("mma.sync.aligned.m16n8k16.row.col.f32.bf16.bf16.f32 "
        "{%0,%1,%2,%3}, {%4,%5,%6,%7}, {%8,%9}, {%0,%1,%2,%3};"
        : "+f"(c[0]), "+f"(c[1]), "+f"(c[2]), "+f"(c[3])
        : "r"(a[0]), "r"(a[1]), "r"(a[2]), "r"(a[3]), "r"(b[0]), "r"(b[1]));
}
__device__ __forceinline__ void mma_tf32(float* c, const uint32_t* a, const uint32_t* b) {
    asm volatile("mma.sync.aligned.m16n8k8.row.col.f32.tf32.tf32.f32 "
        "{%0,%1,%2,%3}, {%4,%5,%6,%7}, {%8,%9}, {%0,%1,%2,%3};"
        : "+f"(c[0]), "+f"(c[1]), "+f"(c[2]), "+f"(c[3])
        : "r"(a[0]), "r"(a[1]), "r"(a[2]), "r"(a[3]), "r"(b[0]), "r"(b[1]));
}
#define CP_ASYNC16(smem, gptr) \
    asm volatile("cp.async.cg.shared.global [%0], [%1], 16;" :: "r"(smem), "l"(gptr) : "memory")
#define CP_COMMIT() asm volatile("cp.async.commit_group;" ::: "memory")
#define CP_WAIT(n)  asm volatile("cp.async.wait_group %0;" :: "n"(n) : "memory")

// ================= scratch =================
static __device__ float g_x [B_*N_*FP];
static __device__ float g_x1[B_*N_*FP];
static __device__ float g_x2[B_*N_*FP];
static __device__ float g_x2b[B_*N_*FP];                  // K-split partial (pass 2)
static __device__ float g_s2[NTOT*U_];
static __device__ float g_u [NTOT*U_];
static __device__ __nv_bfloat16 g_adp[(size_t)B_*N_*N_];  // bf16 adp written by pass 1
static __device__ __nv_bfloat16 g_xt[B_*NB*N_];           // transposed bf16 features
static __device__ uint32_t g_wp_ru[216*128];
static __device__ uint32_t g_wp_c [216*64];
static __device__ int   g_cnt[N_];
static __device__ int   g_off[N_ + 1];
static __device__ int   g_ccol[E_];
static __device__ float g_cval[E_];

// ================= prep: zero g_cnt + W permute/tf32 (independent elementwise) ======
__global__ void k_prep(const float* __restrict__ W_ru, const float* __restrict__ W_c) {
    int idx = blockIdx.x * blockDim.x + threadIdx.x;
    if (idx < N_) g_cnt[idx] = 0;
    if (idx < 216 * 128) {
        int kk = idx >> 7, o = idx & 127;
        int m = kk / 72, f = kk - m * 72;
        float v = (f < F_) ? W_ru[(f * 3 + m) * 128 + o] : 0.f;
        g_wp_ru[idx] = f2tf32(v);
    } else {
        int j = idx - 216 * 128;
        if (j < 216 * 64) {
            int kk = j >> 6, o = j & 63;
            int m = kk / 72, f = kk - m * 72;
            float v = (f < F_) ? W_c[(f * 3 + m) * 64 + o] : 0.f;
            g_wp_c[j] = f2tf32(v);
        }
    }
}

// ================= CSR scan =================
__global__ __launch_bounds__(1024) void k_scan() {
    __shared__ int sa[N_], sb[N_];
    int t = threadIdx.x;
    sa[t] = g_cnt[t];
    sa[t + 1024] = g_cnt[t + 1024];
    __syncthreads();
    int* src = sa; int* dst = sb;
    for (int d = 1; d < N_; d <<= 1) {
        for (int k = t; k < N_; k += 1024) {
            int v = src[k];
            if (k >= d) v += src[k - d];
            dst[k] = v;
        }
        __syncthreads();
        int* tmp = src; src = dst; dst = tmp;
    }
    int e0 = (t == 0) ? 0 : src[t - 1];
    int e1 = src[t + 1023];
    g_off[t] = e0;        g_off[t + 1024] = e1;
    g_cnt[t] = e0;        g_cnt[t + 1024] = e1;
    if (t == 0) g_off[N_] = src[N_ - 1];
}

// ================= fused build: g_x (fp32) + g_xt (bf16) [+ hist in pass 1] ========
template <bool USE_S2>
__global__ __launch_bounds__(256) void k_build_xt(const float* __restrict__ in,
                                                  const float* __restrict__ st,
                                                  const int* __restrict__ rows) {
    __shared__ float sx[64][69];
    int tid = threadIdx.x;
    int b   = blockIdx.x >> 5;
    int m0  = (blockIdx.x & 31) << 6;
    int bn0 = (b << 11) + m0;

    if (!USE_S2) {
        // fused histogram: blocks 0..127 cover all E edges (256 each)
        if (blockIdx.x < E_ / 256) {
            int e = blockIdx.x * 256 + tid;
            atomicAdd(&g_cnt[rows[e]], 1);
        }
    }

    const float* S = USE_S2 ? g_s2 : st;
    for (int q = tid; q < 64 * U_; q += 256) {
        int r = q >> 6, c = q & 63;
        sx[r][2 + c] = S[(bn0 + r) * U_ + c];
    }
    for (int q = tid; q < 64 * DIN; q += 256) {
        int r = q >> 1, j = q & 1;
        sx[r][j] = in[(b << 12) + (m0 + r) * DIN + j];
    }
    __syncthreads();
    for (int q = tid; q < 64 * FP; q += 256) {
        int r = q / FP, f = q - r * FP;
        g_x[(size_t)(bn0 + r) * FP + f] = (f < F_) ? sx[r][f] : 0.f;
    }
    for (int q = tid; q < NB * 64; q += 256) {
        int f = q >> 6, ml = q & 63;
        float v = (f < F_) ? sx[ml][f] : 0.f;
        g_xt[((size_t)(b * NB + f) << 11) + m0 + ml] = __float2bfloat16(v);
    }
}

// ================= spmm (standalone — amortizes edges across all 16 batches) ========
__global__ __launch_bounds__(128) void k_spmm() {
    int n = blockIdx.x;
    int s = g_off[n], e = g_off[n + 1];
    int tid = threadIdx.x;
    float acc[9];
#pragma unroll
    for (int j = 0; j < 9; j++) acc[j] = 0.f;

    __shared__ int   scol[128];
    __shared__ float sval[128];

    for (int base = s; base < e; base += 128) {
        int cnt = min(128, e - base);
        if (tid < cnt) { scol[tid] = g_ccol[base + tid]; sval[tid] = g_cval[base + tid]; }
        __syncthreads();
        for (int t = 0; t < cnt; t++) {
            int   c = scol[t];
            float v = sval[t];
#pragma unroll
            for (int j = 0; j < 9; j++) {
                int i = tid + j * 128;
                if (i < B_ * F_) {
                    int bb = i / F_, f = i - bb * F_;
                    acc[j] += v * g_x[(bb * N_ + c) * FP + f];
                }
            }
        }
        __syncthreads();
    }
#pragma unroll
    for (int j = 0; j < 9; j++) {
        int i = tid + j * 128;
        if (i < B_ * F_) {
            int bb = i / F_, f = i - bb * F_;
            g_x1[(bb * N_ + n) * FP + f] = acc[j];
        }
    }
}

// ================= gemm pass 1: cp.async staging + cvt + MMA + g_adp [+ scatter] ====
#define KT       32
#define TILES    (N_ / KT)
#define ASTRIDE  40
#define BSTRIDE  40
#define CSTG     3
#define SF_STG   (128 * KT * 4)
#define SB1_STG  (NB * BSTRIDE * 2)
#define SABF_B   (128 * ASTRIDE * 2)
#define GEMM1_SMEM (CSTG * (SF_STG + SB1_STG) + SABF_B)   // 78592 B

__global__ __launch_bounds__(256) void k_gemm_cvt(const float* __restrict__ adp,
                                                  const int* __restrict__ rows,
                                                  const int* __restrict__ cols,
                                                  const float* __restrict__ vals) {
    extern __shared__ char smem1[];
    uint32_t sFaddr  = smem_to_u32(smem1);
    uint32_t sBaddr  = sFaddr + CSTG * SF_STG;
    uint32_t sAbf    = sBaddr + CSTG * SB1_STG;

    int tid  = threadIdx.x;
    int lane = tid & 31;
    int wid  = tid >> 5;
    int wm   = wid >> 1, wn = wid & 1;
    int m0w  = wm * 32, n0w = wn * 40;

    // fused CSR scatter: blocks 0..127 place 256 edges each (independent of gemm work)
    if (blockIdx.x < E_ / 256) {
        int e = blockIdx.x * 256 + tid;
        int r = rows[e];
        int p = atomicAdd(&g_cnt[r], 1);
        g_ccol[p] = cols[e];
        g_cval[p] = vals[e];
    }

    int b  = blockIdx.x >> 4;
    int m0 = (blockIdx.x & 15) << 7;
    const float* A = adp + (size_t)b * N_ * N_;
    __nv_bfloat16* Aout = g_adp + (size_t)b * N_ * N_;
    const __nv_bfloat16* XT = g_xt + ((size_t)b * NB << 11);

    float acc[2][5][4];
#pragma unroll
    for (int mi = 0; mi < 2; mi++)
#pragma unroll
        for (int ni = 0; ni < 5; ni++)
#pragma unroll
            for (int c = 0; c < 4; c++) acc[mi][ni][c] = 0.f;

    int br0 = tid >> 2, bc0 = tid & 3;
    int br1 = (256 + tid) >> 2, bc1 = (256 + tid) & 3;

    auto issue_stage = [&](int slot, int tile) {
        uint32_t fS = sFaddr + slot * SF_STG;
        uint32_t bS = sBaddr + slot * SB1_STG;
        int kt = tile * KT;
#pragma unroll
        for (int i = 0; i < 4; i++) {
            int q = tid + i * 256;
            int row = q >> 3, c4 = q & 7;
            CP_ASYNC16(fS + (uint32_t)(row * KT + c4 * 4) * 4,
                       A + (((size_t)(m0 + row)) << 11) + kt + c4 * 4);
        }
        CP_ASYNC16(bS + (uint32_t)(br0 * BSTRIDE + bc0 * 8) * 2,
                   XT + (((size_t)br0) << 11) + kt + bc0 * 8);
        if (tid < 64)
            CP_ASYNC16(bS + (uint32_t)(br1 * BSTRIDE + bc1 * 8) * 2,
                       XT + (((size_t)br1) << 11) + kt + bc1 * 8);
    };

#pragma unroll
    for (int s = 0; s < CSTG; s++) {
        issue_stage(s, s);
        CP_COMMIT();
    }

    int slot = 0;
    for (int t = 0; t < TILES; t++) {
        CP_WAIT(CSTG - 1);
        __syncthreads();

        uint32_t fS = sFaddr + slot * SF_STG;
        int kt = t * KT;
#pragma unroll
        for (int i = 0; i < 4; i++) {
            int q = tid + i * 256;
            int row = q >> 3, c4 = q & 7;
            float vx, vy, vz, vw;
            asm volatile("ld.shared.v4.f32 {%0,%1,%2,%3}, [%4];"
                : "=f"(vx), "=f"(vy), "=f"(vz), "=f"(vw)
                : "r"(fS + (uint32_t)(row * KT + c4 * 4) * 4));
            uint32_t p0 = pack_bf16x2(vx, vy);
            uint32_t p1 = pack_bf16x2(vz, vw);
            asm volatile("st.shared.v2.b32 [%0], {%1, %2};"
                :: "r"(sAbf + (uint32_t)(row * ASTRIDE + c4 * 4) * 2), "r"(p0), "r"(p1) : "memory");
            *(uint2*)&Aout[(((size_t)(m0 + row)) << 11) + kt + c4 * 4] = make_uint2(p0, p1);
        }
        __syncthreads();

        uint32_t bS = sBaddr + slot * SB1_STG;
#pragma unroll
        for (int ks = 0; ks < 2; ks++) {
            uint32_t afr[2][4];
#pragma unroll
            for (int mi = 0; mi < 2; mi++) {
                uint32_t ad = sAbf + (uint32_t)((m0w + mi * 16 + (lane & 15)) * ASTRIDE
                              + ks * 16 + (lane >> 4) * 8) * 2;
                ldmatrix_x4(afr[mi], ad);
            }
            uint32_t bfr[5][2];
#pragma unroll
            for (int ni = 0; ni < 5; ni++) {
                uint32_t bd = bS + (uint32_t)((n0w + ni * 8 + (lane & 7)) * BSTRIDE
                              + ks * 16 + ((lane >> 3) & 1) * 8) * 2;
                ldmatrix_x2(bfr[ni], bd);
            }
#pragma unroll
            for (int mi = 0; mi < 2; mi++)
#pragma unroll
                for (int ni = 0; ni < 5; ni++)
                    mma_bf16(acc[mi][ni], afr[mi], bfr[ni]);
        }
        __syncthreads();

        if (t + CSTG < TILES) issue_stage(slot, t + CSTG);
        CP_COMMIT();
        if (++slot == CSTG) slot = 0;
    }

#pragma unroll
    for (int mi = 0; mi < 2; mi++) {
#pragma unroll
        for (int ni = 0; ni < 5; ni++) {
            int col = n0w + ni * 8 + (lane & 3) * 2;
            if (col < F_) {
                int r0 = m0 + m0w + mi * 16 + (lane >> 2);
                size_t base0 = ((size_t)(b << 11) + r0) * FP + col;
                *(float2*)&g_x2[base0]          = make_float2(acc[mi][ni][0], acc[mi][ni][1]);
                *(float2*)&g_x2[base0 + 8 * FP] = make_float2(acc[mi][ni][2], acc[mi][ni][3]);
            }
        }
    }
}

// ================= gemm pass 2: cp.async 3-stage bf16, K-split x2, reads g_adp ======
#define STG2     3
#define TILES2   (N_ / KT / 2)
#define A2_STG   (128 * ASTRIDE * 2)
#define B2_STG   (NB  * BSTRIDE * 2)
#define GEMM2_SMEM (STG2 * (A2_STG + B2_STG))   // 49920 B

__global__ __launch_bounds__(256) void k_gemm_bf() {
    extern __shared__ char smem[];
    uint32_t sAaddr = smem_to_u32(smem);
    uint32_t sBaddr = sAaddr + STG2 * A2_STG;

    int tid  = threadIdx.x;
    int lane = tid & 31;
    int wid  = tid >> 5;
    int wm   = wid >> 1, wn = wid & 1;
    int m0w  = wm * 32, n0w = wn * 40;

    int b  = blockIdx.x >> 5;
    int m0 = ((blockIdx.x >> 1) & 15) << 7;
    int kh = blockIdx.x & 1;
    int kbase = kh << 10;
    const __nv_bfloat16* Ab = g_adp + (size_t)b * N_ * N_;
    const __nv_bfloat16* XT = g_xt + ((size_t)b * NB << 11);
    float* X2out = kh ? g_x2b : g_x2;

    float acc[2][5][4];
#pragma unroll
    for (int mi = 0; mi < 2; mi++)
#pragma unroll
        for (int ni = 0; ni < 5; ni++)
#pragma unroll
            for (int c = 0; c < 4; c++) acc[mi][ni][c] = 0.f;

    int ar0 = tid >> 2,         ac0 = tid & 3;
    int ar1 = (256 + tid) >> 2, ac1 = (256 + tid) & 3;
    int br0 = tid >> 2, bc0 = tid & 3;
    int br1 = (256 + tid) >> 2, bc1 = (256 + tid) & 3;

    auto issue_stage = [&](int slot, int tile) {
        uint32_t aS = sAaddr + slot * A2_STG;
        uint32_t bS = sBaddr + slot * B2_STG;
        int kt = kbase + tile * KT;
        CP_ASYNC16(aS + (uint32_t)(ar0 * ASTRIDE + ac0 * 8) * 2,
                   Ab + (((size_t)(m0 + ar0)) << 11) + kt + ac0 * 8);
        CP_ASYNC16(aS + (uint32_t)(ar1 * ASTRIDE + ac1 * 8) * 2,
                   Ab + (((size_t)(m0 + ar1)) << 11) + kt + ac1 * 8);
        CP_ASYNC16(bS + (uint32_t)(br0 * BSTRIDE + bc0 * 8) * 2,
                   XT + (((size_t)br0) << 11) + kt + bc0 * 8);
        if (tid < 64)
            CP_ASYNC16(bS + (uint32_t)(br1 * BSTRIDE + bc1 * 8) * 2,
                       XT + (((size_t)br1) << 11) + kt + bc1 * 8);
    };

#pragma unroll
    for (int s = 0; s < STG2; s++) {
        issue_stage(s, s);
        CP_COMMIT();
    }

    int slot = 0;
    for (int t = 0; t < TILES2; t++) {
        CP_WAIT(STG2 - 1);
        __syncthreads();

        uint32_t aS = sAaddr + slot * A2_STG;
        uint32_t bS = sBaddr + slot * B2_STG;
#pragma unroll
        for (int ks = 0; ks < 2; ks++) {
            uint32_t afr[2][4];
#pragma unroll
            for (int mi = 0; mi < 2; mi++) {
                uint32_t ad = aS + (uint32_t)((m0w + mi * 16 + (lane & 15)) * ASTRIDE
                              + ks * 16 + (lane >> 4) * 8) * 2;
                ldmatrix_x4(afr[mi], ad);
            }
            uint32_t bfr[5][2];
#pragma unroll
            for (int ni = 0; ni < 5; ni++) {
                uint32_t bd = bS + (uint32_t)((n0w + ni * 8 + (lane & 7)) * BSTRIDE
                              + ks * 16 + ((lane >> 3) & 1) * 8) * 2;
                ldmatrix_x2(bfr[ni], bd);
            }
#pragma unroll
            for (int mi = 0; mi < 2; mi++)
#pragma unroll
                for (int ni = 0; ni < 5; ni++)
                    mma_bf16(acc[mi][ni], afr[mi], bfr[ni]);
        }
        __syncthreads();

        if (t + STG2 < TILES2) issue_stage(slot, t + STG2);
        CP_COMMIT();
        if (++slot == STG2) slot = 0;
    }

#pragma unroll
    for (int mi = 0; mi < 2; mi++) {
#pragma unroll
        for (int ni = 0; ni < 5; ni++) {
            int col = n0w + ni * 8 + (lane & 3) * 2;
            if (col < F_) {
                int r0 = m0 + m0w + mi * 16 + (lane >> 2);
                size_t base0 = ((size_t)(b << 11) + r0) * FP + col;
                *(float2*)&X2out[base0]          = make_float2(acc[mi][ni][0], acc[mi][ni][1]);
                *(float2*)&X2out[base0 + 8 * FP] = make_float2(acc[mi][ni][2], acc[mi][ni][3]);
            }
        }
    }
}

// ================= output GEMM (tf32 tensor cores) =================
// IS_RU: x2 = g_x2 (full, from pass 1). !IS_RU: x2 = g_x2 + g_x2b (K-split partials).
template <int ON, bool IS_RU>
__global__ __launch_bounds__(256) void k_out_tc(const uint32_t* __restrict__ Wp,
                                                const float* __restrict__ hx,
                                                float* __restrict__ dout) {
    extern __shared__ uint32_t sm[];
    const int ASTR = 76;
    const int BSTR = ON + 4;
    uint32_t* sA = sm;
    uint32_t* sB = sm + 64 * ASTR;

    const int WNW   = ON / 32;
    const int MFRAG = (ON == 128) ? 2 : 1;
    const int WTM   = MFRAG * 16;

    int tid = threadIdx.x, lane = tid & 31, wid = tid >> 5;
    int wn = wid % WNW, wm = wid / WNW;
    int row0 = blockIdx.x * 64;
    int g = lane >> 2, tt = lane & 3;

    for (int q = tid; q < 64 * 6; q += 256) {
        int r = q / 6, c = 66 + (q - r * 6);
        sA[r * ASTR + c] = 0;
    }

    float acc[MFRAG][4][4];
#pragma unroll
    for (int mi = 0; mi < MFRAG; mi++)
#pragma unroll
        for (int ni = 0; ni < 4; ni++)
#pragma unroll
            for (int c = 0; c < 4; c++) acc[mi][ni][c] = 0.f;

    for (int m = 0; m < 3; m++) {
        const float* Xb = (m == 0) ? g_x : (m == 1) ? g_x1 : g_x2;
        bool sum2 = (!IS_RU) && (m == 2);
        __syncthreads();
        for (int q = tid; q < 64 * 17; q += 256) {
            int r = q / 17, p = q - r * 17;
            size_t src = (size_t)(row0 + r) * FP;
            uint32_t dst = r * ASTR;
            if (p < 16) {
                float4 v = *(const float4*)&Xb[src + p * 4];
                if (sum2) {
                    float4 w = *(const float4*)&g_x2b[src + p * 4];
                    v.x += w.x; v.y += w.y; v.z += w.z; v.w += w.w;
                }
                uint32_t t0 = f2tf32(v.x), t1 = f2tf32(v.y), t2 = f2tf32(v.z), t3 = f2tf32(v.w);
                *(uint4*)&sA[dst + p * 4] = make_uint4(t0, t1, t2, t3);
            } else {
                float2 v = *(const float2*)&Xb[src + 64];
                if (sum2) {
                    float2 w = *(const float2*)&g_x2b[src + 64];
                    v.x += w.x; v.y += w.y;
                }
                sA[dst + 64] = f2tf32(v.x);
                sA[dst + 65] = f2tf32(v.y);
            }
        }
        for (int q = tid; q < 72 * (ON / 4); q += 256) {
            int r = q / (ON / 4), c4 = q - r * (ON / 4);
            uint4 v = *(const uint4*)&Wp[(m * 72 + r) * ON + c4 * 4];
            *(uint4*)&sB[r * BSTR + c4 * 4] = v;
        }
        __syncthreads();
#pragma unroll
        for (int kt = 0; kt < 9; kt++) {
            int k0 = kt * 8;
            uint32_t af[MFRAG][4];
#pragma unroll
            for (int mi = 0; mi < MFRAG; mi++) {
                int r0 = wm * WTM + mi * 16 + g;
                int kc = k0 + tt;
                af[mi][0] = sA[r0 * ASTR + kc];
                af[mi][1] = sA[(r0 + 8) * ASTR + kc];
                af[mi][2] = sA[r0 * ASTR + kc + 4];
                af[mi][3] = sA[(r0 + 8) * ASTR + kc + 4];
            }
            uint32_t bf[4][2];
#pragma unroll
            for (int ni = 0; ni < 4; ni++) {
                int col = wn * 32 + ni * 8 + g;
                int kr = k0 + tt;
                bf[ni][0] = sB[kr * BSTR + col];
                bf[ni][1] = sB[(kr + 4) * BSTR + col];
            }
#pragma unroll
            for (int mi = 0; mi < MFRAG; mi++)
#pragma unroll
                for (int ni = 0; ni < 4; ni++)
                    mma_tf32(acc[mi][ni], af[mi], bf[ni]);
        }
    }

#pragma unroll
    for (int mi = 0; mi < MFRAG; mi++) {
#pragma unroll
        for (int ni = 0; ni < 4; ni++) {
            int r0  = row0 + wm * WTM + mi * 16 + g;
            int col = wn * 32 + ni * 8 + tt * 2;
#pragma unroll
            for (int h = 0; h < 2; h++) {
                int bn = r0 + h * 8;
#pragma unroll
                for (int cc = 0; cc < 2; cc++) {
                    float v = acc[mi][ni][h * 2 + cc];
                    int o = col + cc;
                    if (IS_RU) {
                        float s = 1.f / (1.f + expf(-v));
                        if (o < U_) g_s2[bn * U_ + o] = s * hx[bn * U_ + o];
                        else        g_u [bn * U_ + (o - U_)] = s;
                    } else {
                        float cv = tanhf(v);
                        int idx = bn * U_ + o;
                        float u = g_u[idx], hh = hx[idx];
                        dout[idx] = u * hh + (1.f - u) * cv;
                    }
                }
            }
        }
    }
}

// ================= launch =================
extern "C" void kernel_launch(void* const* d_in, const int* in_sizes, int n_in,
                              void* d_out, int out_size) {
    const float* inputs = (const float*)d_in[0];
    const float* hx     = (const float*)d_in[1];
    const float* adp    = (const float*)d_in[2];
    const int*   rows   = (const int*)d_in[3];
    const int*   cols   = (const int*)d_in[4];
    const float* vals   = (const float*)d_in[5];
    const float* W_ru   = (const float*)d_in[6];
    const float* W_c    = (const float*)d_in[7];
    float* out = (float*)d_out;
    (void)in_sizes; (void)n_in; (void)out_size;

    const int SMEM_RU = (64 * 76 + 72 * 132) * 4;
    const int SMEM_C  = (64 * 76 + 72 * 68) * 4;
    cudaFuncSetAttribute(k_gemm_cvt, cudaFuncAttributeMaxDynamicSharedMemorySize, GEMM1_SMEM);
    cudaFuncSetAttribute(k_gemm_bf, cudaFuncAttributeMaxDynamicSharedMemorySize, GEMM2_SMEM);
    cudaFuncSetAttribute(k_out_tc<128, true>, cudaFuncAttributeMaxDynamicSharedMemorySize, SMEM_RU);
    cudaFuncSetAttribute(k_out_tc<64, false>, cudaFuncAttributeMaxDynamicSharedMemorySize, SMEM_C);

    uint32_t* wp_ru; cudaGetSymbolAddress((void**)&wp_ru, g_wp_ru);
    uint32_t* wp_c;  cudaGetSymbolAddress((void**)&wp_c,  g_wp_c);

    // ordered so pass-1 gemm is the 4th launch (ncu profiling slot)
    k_prep    <<<162, 256>>>(W_ru, W_c);                   // zero g_cnt + wperm
    k_build_xt<false><<<512, 256>>>(inputs, hx, rows);     // build#1 + hist
    k_scan    <<<1, 1024>>>();
    k_gemm_cvt<<<256, 256, GEMM1_SMEM>>>(adp, rows, cols, vals);  // profiled (+scatter)
    k_spmm    <<<N_, 128>>>();
    k_out_tc<128, true><<<NTOT / 64, 256, SMEM_RU>>>(wp_ru, hx, out);

    // ---- gconv #2 : candidate c ----
    k_build_xt<true><<<512, 256>>>(inputs, hx, rows);
    k_gemm_bf <<<512, 256, GEMM2_SMEM>>>();
    k_spmm    <<<N_, 128>>>();
    k_out_tc<64, false><<<NTOT / 64, 256, SMEM_C>>>(wp_c, hx, out);
}